// round 14
// baseline (speedup 1.0000x reference)
#include <cuda_runtime.h>

// Problem constants (B=64, S=4096, D=256)
#define B_ 64
#define S_ 4096
#define D_ 256
#define NSPLIT 8
#define CHUNK (S_ / NSPLIT)             // 512 rows per block
#define NWARPS 8
#define THREADS 256
#define ROWS_PER_WARP (CHUNK / NWARPS)  // 64
#define RB 4                            // rows per warp-iteration (ILP batch)

// Scratch: per (batch, split) partial accumulator + weight sum.
__device__ float g_acc[B_ * NSPLIT][D_];
__device__ float g_lsum[B_ * NSPLIT];
// Monotonic arrival counter per batch (never reset; mod-NSPLIT detects last
// block of each call — graph-replay safe, deterministic output).
__device__ unsigned int g_cnt[B_];

// w = exp(tanh(x)) = e * exp(-2/(e^{2x}+1))
// Branch-free, robust: x -> -inf gives e^-1, x -> +inf gives e (t=inf -> div=0).
__device__ __forceinline__ float exp_tanh(float x) {
    float t = __expf(2.0f * x);
    return 2.718281828f * __expf(__fdividef(-2.0f, t + 1.0f));
}

__global__ __launch_bounds__(THREADS) void att_fused(
    const float* __restrict__ aspect,   // [B, 1, D]
    const float* __restrict__ memory,   // [B, S, D]
    const float* __restrict__ W,        // [2D, 1]
    const float* __restrict__ bias,     // [1]
    float* __restrict__ out)            // [B, D]
{
    const int blk   = blockIdx.x;
    const int batch = blk / NSPLIT;
    const int split = blk % NSPLIT;
    const int tid   = threadIdx.x;
    const int warp  = tid >> 5;
    const int lane  = tid & 31;

    __shared__ float s_acc[D_];
    __shared__ float s_l[NWARPS];
    __shared__ unsigned int s_last;

    // Zero the block accumulator now; visibility guaranteed by the barrier
    // AFTER the main loop (no entry barrier needed).
    s_acc[tid] = 0.0f;

    // ---- per-warp redundant aspect bias: no smem, no __syncthreads ----
    // lane l covers aspect elements l, l+32, ..., l+224.
    float abias;
    {
        const float* ab = aspect + batch * D_;
        float p = 0.0f;
        #pragma unroll
        for (int k = 0; k < 8; k++)
            p += ab[lane + 32 * k] * W[D_ + lane + 32 * k];
        #pragma unroll
        for (int o = 16; o; o >>= 1) p += __shfl_xor_sync(0xffffffffu, p, o);
        abias = p + bias[0];
    }

    // ---- Wm in registers: lane l holds W4[l] and W4[32+l] ----
    const float4* W4 = (const float4*)W;
    const float4 wm0 = W4[lane];
    const float4 wm1 = W4[32 + lane];

    const float4* mem4 = (const float4*)memory
                       + (size_t)batch * (S_ * (D_ / 4))
                       + (size_t)split * CHUNK * (D_ / 4);

    float4 a0 = make_float4(0.f, 0.f, 0.f, 0.f);
    float4 a1 = make_float4(0.f, 0.f, 0.f, 0.f);
    float lsum = 0.0f;

    // RB independent rows per iteration: 2*RB front-batched LDG.128, RB
    // independent shuffle-reduction chains that pipeline. (R2's exact body.)
    #pragma unroll 2
    for (int i = 0; i < ROWS_PER_WARP; i += RB) {
        float4 v0[RB], v1[RB];
        #pragma unroll
        for (int j = 0; j < RB; j++) {
            const float4* r = mem4 + (size_t)((i + j) * NWARPS + warp) * (D_ / 4);
            v0[j] = r[lane];
            v1[j] = r[32 + lane];
        }

        float dot[RB];
        #pragma unroll
        for (int j = 0; j < RB; j++)
            dot[j] = v0[j].x * wm0.x + v0[j].y * wm0.y + v0[j].z * wm0.z + v0[j].w * wm0.w
                   + v1[j].x * wm1.x + v1[j].y * wm1.y + v1[j].z * wm1.z + v1[j].w * wm1.w;

        #pragma unroll
        for (int o = 16; o; o >>= 1) {
            #pragma unroll
            for (int j = 0; j < RB; j++)
                dot[j] += __shfl_xor_sync(0xffffffffu, dot[j], o);
        }

        #pragma unroll
        for (int j = 0; j < RB; j++) {
            const float w = exp_tanh(dot[j] + abias);
            lsum += w;
            a0.x += w * v0[j].x; a0.y += w * v0[j].y;
            a0.z += w * v0[j].z; a0.w += w * v0[j].w;
            a1.x += w * v1[j].x; a1.y += w * v1[j].y;
            a1.z += w * v1[j].z; a1.w += w * v1[j].w;
        }
    }

    // Barrier: makes the entry-time s_acc zeroing visible before the atomics
    // (this is the FIRST block-wide sync in the kernel).
    __syncthreads();

    // ---- combine 8 warps via smem atomics (one shot) ----
    atomicAdd(&s_acc[lane * 4 + 0], a0.x);
    atomicAdd(&s_acc[lane * 4 + 1], a0.y);
    atomicAdd(&s_acc[lane * 4 + 2], a0.z);
    atomicAdd(&s_acc[lane * 4 + 3], a0.w);
    atomicAdd(&s_acc[128 + lane * 4 + 0], a1.x);
    atomicAdd(&s_acc[128 + lane * 4 + 1], a1.y);
    atomicAdd(&s_acc[128 + lane * 4 + 2], a1.z);
    atomicAdd(&s_acc[128 + lane * 4 + 3], a1.w);
    if (lane == 0) s_l[warp] = lsum;
    __syncthreads();

    // ---- publish this block's partial ----
    g_acc[blk][tid] = s_acc[tid];
    if (tid == 0) {
        float l = 0.f;
        #pragma unroll
        for (int w = 0; w < NWARPS; w++) l += s_l[w];
        g_lsum[blk] = l;
    }

    // ---- last block of this batch combines (threadfence-reduction pattern) ----
    __threadfence();
    if (tid == 0) {
        unsigned int old = atomicAdd(&g_cnt[batch], 1u);
        s_last = (((old + 1u) % NSPLIT) == 0u) ? 1u : 0u;
    }
    __syncthreads();

    if (s_last) {
        float acc = 0.f, l = 0.f;
        #pragma unroll
        for (int sp = 0; sp < NSPLIT; sp++) {
            acc += g_acc[batch * NSPLIT + sp][tid];
            l   += g_lsum[batch * NSPLIT + sp];
        }
        out[batch * D_ + tid] = acc / l;
    }
}

extern "C" void kernel_launch(void* const* d_in, const int* in_sizes, int n_in,
                              void* d_out, int out_size)
{
    const float* aspect = (const float*)d_in[0];   // [B,1,D]
    const float* memory = (const float*)d_in[1];   // [B,S,D]
    const float* W      = (const float*)d_in[2];   // [2D,1]
    const float* bias   = (const float*)d_in[3];   // [1]
    float* out = (float*)d_out;                    // [B,D]

    att_fused<<<B_ * NSPLIT, THREADS>>>(aspect, memory, W, bias, out);
}

// round 15
// speedup vs baseline: 1.1712x; 1.1712x over previous
#include <cuda_runtime.h>

// Problem constants (B=64, S=4096, D=256)
#define B_ 64
#define S_ 4096
#define D_ 256
#define NSPLIT 8
#define CHUNK (S_ / NSPLIT)             // 512 rows per block
#define NWARPS 8
#define THREADS 256
#define ROWS_PER_WARP (CHUNK / NWARPS)  // 64
#define RB 4                            // rows per warp-iteration (ILP batch)

// Scratch: per (batch, split) partial accumulator + weight sum.
__device__ float g_acc[B_ * NSPLIT][D_];
__device__ float g_lsum[B_ * NSPLIT];
// Monotonic arrival counter per batch (never reset; mod-NSPLIT detects last
// block of each call — graph-replay safe, deterministic output).
__device__ unsigned int g_cnt[B_];

// w = exp(tanh(x)) = e * exp(-2/(e^{2x}+1))
// Branch-free, robust: x -> -inf gives e^-1, x -> +inf gives e (t=inf -> div=0).
__device__ __forceinline__ float exp_tanh(float x) {
    float t = __expf(2.0f * x);
    return 2.718281828f * __expf(__fdividef(-2.0f, t + 1.0f));
}

__global__ __launch_bounds__(THREADS) void att_fused(
    const float* __restrict__ aspect,   // [B, 1, D]
    const float* __restrict__ memory,   // [B, S, D]
    const float* __restrict__ W,        // [2D, 1]
    const float* __restrict__ bias,     // [1]
    float* __restrict__ out)            // [B, D]
{
    const int blk   = blockIdx.x;
    const int batch = blk / NSPLIT;
    const int split = blk % NSPLIT;
    const int tid   = threadIdx.x;
    const int warp  = tid >> 5;
    const int lane  = tid & 31;

    __shared__ float s_red[NWARPS];
    __shared__ float s_abias;
    __shared__ float s_acc[D_];
    __shared__ float s_l[NWARPS];
    __shared__ unsigned int s_last;

    // ---- aspect bias: dot(aspect[batch], Wa) + b  (Wa = W[D:2D]) ----
    {
        float p = aspect[batch * D_ + tid] * W[D_ + tid];
        #pragma unroll
        for (int o = 16; o; o >>= 1) p += __shfl_xor_sync(0xffffffffu, p, o);
        if (lane == 0) s_red[warp] = p;
    }
    s_acc[tid] = 0.0f;
    __syncthreads();
    if (tid == 0) {
        float s = bias[0];
        #pragma unroll
        for (int w = 0; w < NWARPS; w++) s += s_red[w];
        s_abias = s;
    }
    __syncthreads();
    const float abias = s_abias;

    // ---- Wm in registers: lane l holds W4[l] and W4[32+l] ----
    const float4* W4 = (const float4*)W;
    const float4 wm0 = W4[lane];
    const float4 wm1 = W4[32 + lane];

    const float4* mem4 = (const float4*)memory
                       + (size_t)batch * (S_ * (D_ / 4))
                       + (size_t)split * CHUNK * (D_ / 4);

    float4 a0 = make_float4(0.f, 0.f, 0.f, 0.f);
    float4 a1 = make_float4(0.f, 0.f, 0.f, 0.f);
    float lsum = 0.0f;

    // RB independent rows per iteration: 2*RB front-batched LDG.128, RB
    // independent shuffle-reduction chains that pipeline.
    #pragma unroll 2
    for (int i = 0; i < ROWS_PER_WARP; i += RB) {
        float4 v0[RB], v1[RB];
        #pragma unroll
        for (int j = 0; j < RB; j++) {
            const float4* r = mem4 + (size_t)((i + j) * NWARPS + warp) * (D_ / 4);
            v0[j] = r[lane];
            v1[j] = r[32 + lane];
        }

        float dot[RB];
        #pragma unroll
        for (int j = 0; j < RB; j++)
            dot[j] = v0[j].x * wm0.x + v0[j].y * wm0.y + v0[j].z * wm0.z + v0[j].w * wm0.w
                   + v1[j].x * wm1.x + v1[j].y * wm1.y + v1[j].z * wm1.z + v1[j].w * wm1.w;

        #pragma unroll
        for (int o = 16; o; o >>= 1) {
            #pragma unroll
            for (int j = 0; j < RB; j++)
                dot[j] += __shfl_xor_sync(0xffffffffu, dot[j], o);
        }

        #pragma unroll
        for (int j = 0; j < RB; j++) {
            const float w = exp_tanh(dot[j] + abias);
            lsum += w;
            a0.x += w * v0[j].x; a0.y += w * v0[j].y;
            a0.z += w * v0[j].z; a0.w += w * v0[j].w;
            a1.x += w * v1[j].x; a1.y += w * v1[j].y;
            a1.z += w * v1[j].z; a1.w += w * v1[j].w;
        }
    }

    // ---- combine 8 warps via smem atomics (one shot) ----
    atomicAdd(&s_acc[lane * 4 + 0], a0.x);
    atomicAdd(&s_acc[lane * 4 + 1], a0.y);
    atomicAdd(&s_acc[lane * 4 + 2], a0.z);
    atomicAdd(&s_acc[lane * 4 + 3], a0.w);
    atomicAdd(&s_acc[128 + lane * 4 + 0], a1.x);
    atomicAdd(&s_acc[128 + lane * 4 + 1], a1.y);
    atomicAdd(&s_acc[128 + lane * 4 + 2], a1.z);
    atomicAdd(&s_acc[128 + lane * 4 + 3], a1.w);
    if (lane == 0) s_l[warp] = lsum;
    __syncthreads();

    // ---- publish this block's partial ----
    g_acc[blk][tid] = s_acc[tid];
    if (tid == 0) {
        float l = 0.f;
        #pragma unroll
        for (int w = 0; w < NWARPS; w++) l += s_l[w];
        g_lsum[blk] = l;
    }

    // ---- last block of this batch combines (threadfence-reduction pattern) ----
    __threadfence();
    if (tid == 0) {
        unsigned int old = atomicAdd(&g_cnt[batch], 1u);
        s_last = (((old + 1u) % NSPLIT) == 0u) ? 1u : 0u;
    }
    __syncthreads();

    if (s_last) {
        float acc = 0.f, l = 0.f;
        #pragma unroll
        for (int sp = 0; sp < NSPLIT; sp++) {
            acc += g_acc[batch * NSPLIT + sp][tid];
            l   += g_lsum[batch * NSPLIT + sp];
        }
        out[batch * D_ + tid] = acc / l;
    }
}

extern "C" void kernel_launch(void* const* d_in, const int* in_sizes, int n_in,
                              void* d_out, int out_size)
{
    const float* aspect = (const float*)d_in[0];   // [B,1,D]
    const float* memory = (const float*)d_in[1];   // [B,S,D]
    const float* W      = (const float*)d_in[2];   // [2D,1]
    const float* bias   = (const float*)d_in[3];   // [1]
    float* out = (float*)d_out;                    // [B,D]

    att_fused<<<B_ * NSPLIT, THREADS>>>(aspect, memory, W, bias, out);
}

// round 16
// speedup vs baseline: 1.1775x; 1.0054x over previous
#include <cuda_runtime.h>

// Problem constants (B=64, S=4096, D=256)
#define B_ 64
#define S_ 4096
#define D_ 256
#define NSPLIT 8
#define CHUNK (S_ / NSPLIT)             // 512 rows per block
#define NWARPS 8
#define THREADS 256
#define ROWS_PER_WARP (CHUNK / NWARPS)  // 64
#define RB 4                            // rows per warp-iteration (ILP batch)

// Scratch: per (batch, split) partial accumulator + weight sum.
__device__ float g_acc[B_ * NSPLIT][D_];
__device__ float g_lsum[B_ * NSPLIT];
// Monotonic arrival counter per batch (never reset; mod-NSPLIT detects last
// block of each call — graph-replay safe, deterministic output).
__device__ unsigned int g_cnt[B_];

// w = exp(tanh(x)) = e * exp(-2/(e^{2x}+1))
// Branch-free, robust: x -> -inf gives e^-1, x -> +inf gives e (t=inf -> div=0).
__device__ __forceinline__ float exp_tanh(float x) {
    float t = __expf(2.0f * x);
    return 2.718281828f * __expf(__fdividef(-2.0f, t + 1.0f));
}

__global__ __launch_bounds__(THREADS) void att_fused(
    const float* __restrict__ aspect,   // [B, 1, D]
    const float* __restrict__ memory,   // [B, S, D]
    const float* __restrict__ W,        // [2D, 1]
    const float* __restrict__ bias,     // [1]
    float* __restrict__ out)            // [B, D]
{
    const int blk   = blockIdx.x;
    const int batch = blk / NSPLIT;
    const int split = blk % NSPLIT;
    const int tid   = threadIdx.x;
    const int warp  = tid >> 5;
    const int lane  = tid & 31;

    __shared__ float s_red[NWARPS];
    __shared__ float s_abias;
    __shared__ float s_acc[D_];
    __shared__ float s_l[NWARPS];
    __shared__ unsigned int s_last;

    // ---- aspect bias: dot(aspect[batch], Wa) + b  (Wa = W[D:2D]) ----
    {
        float p = aspect[batch * D_ + tid] * W[D_ + tid];
        #pragma unroll
        for (int o = 16; o; o >>= 1) p += __shfl_xor_sync(0xffffffffu, p, o);
        if (lane == 0) s_red[warp] = p;
    }
    s_acc[tid] = 0.0f;
    __syncthreads();
    if (tid == 0) {
        float s = bias[0];
        #pragma unroll
        for (int w = 0; w < NWARPS; w++) s += s_red[w];
        s_abias = s;
    }
    __syncthreads();
    const float abias = s_abias;

    // ---- Wm in registers: lane l holds W4[l] and W4[32+l] ----
    const float4* W4 = (const float4*)W;
    const float4 wm0 = W4[lane];
    const float4 wm1 = W4[32 + lane];

    const float4* mem4 = (const float4*)memory
                       + (size_t)batch * (S_ * (D_ / 4))
                       + (size_t)split * CHUNK * (D_ / 4);

    float4 a0 = make_float4(0.f, 0.f, 0.f, 0.f);
    float4 a1 = make_float4(0.f, 0.f, 0.f, 0.f);
    float lsum = 0.0f;

    // RB independent rows per iteration: 2*RB front-batched LDG.128, RB
    // independent shuffle-reduction chains that pipeline.
    #pragma unroll 2
    for (int i = 0; i < ROWS_PER_WARP; i += RB) {
        float4 v0[RB], v1[RB];
        #pragma unroll
        for (int j = 0; j < RB; j++) {
            const float4* r = mem4 + (size_t)((i + j) * NWARPS + warp) * (D_ / 4);
            v0[j] = r[lane];
            v1[j] = r[32 + lane];
        }

        float dot[RB];
        #pragma unroll
        for (int j = 0; j < RB; j++)
            dot[j] = v0[j].x * wm0.x + v0[j].y * wm0.y + v0[j].z * wm0.z + v0[j].w * wm0.w
                   + v1[j].x * wm1.x + v1[j].y * wm1.y + v1[j].z * wm1.z + v1[j].w * wm1.w;

        #pragma unroll
        for (int o = 16; o; o >>= 1) {
            #pragma unroll
            for (int j = 0; j < RB; j++)
                dot[j] += __shfl_xor_sync(0xffffffffu, dot[j], o);
        }

        #pragma unroll
        for (int j = 0; j < RB; j++) {
            const float w = exp_tanh(dot[j] + abias);
            lsum += w;
            a0.x += w * v0[j].x; a0.y += w * v0[j].y;
            a0.z += w * v0[j].z; a0.w += w * v0[j].w;
            a1.x += w * v1[j].x; a1.y += w * v1[j].y;
            a1.z += w * v1[j].z; a1.w += w * v1[j].w;
        }
    }

    // ---- combine 8 warps via smem atomics (one shot) ----
    atomicAdd(&s_acc[lane * 4 + 0], a0.x);
    atomicAdd(&s_acc[lane * 4 + 1], a0.y);
    atomicAdd(&s_acc[lane * 4 + 2], a0.z);
    atomicAdd(&s_acc[lane * 4 + 3], a0.w);
    atomicAdd(&s_acc[128 + lane * 4 + 0], a1.x);
    atomicAdd(&s_acc[128 + lane * 4 + 1], a1.y);
    atomicAdd(&s_acc[128 + lane * 4 + 2], a1.z);
    atomicAdd(&s_acc[128 + lane * 4 + 3], a1.w);
    if (lane == 0) s_l[warp] = lsum;
    __syncthreads();

    // ---- publish this block's partial ----
    g_acc[blk][tid] = s_acc[tid];
    if (tid == 0) {
        float l = 0.f;
        #pragma unroll
        for (int w = 0; w < NWARPS; w++) l += s_l[w];
        g_lsum[blk] = l;
    }

    // ---- last block of this batch combines (threadfence-reduction pattern) ----
    __threadfence();
    if (tid == 0) {
        unsigned int old = atomicAdd(&g_cnt[batch], 1u);
        s_last = (((old + 1u) % NSPLIT) == 0u) ? 1u : 0u;
    }
    __syncthreads();

    if (s_last) {
        float acc = 0.f, l = 0.f;
        #pragma unroll
        for (int sp = 0; sp < NSPLIT; sp++) {
            acc += g_acc[batch * NSPLIT + sp][tid];
            l   += g_lsum[batch * NSPLIT + sp];
        }
        out[batch * D_ + tid] = acc / l;
    }
}

extern "C" void kernel_launch(void* const* d_in, const int* in_sizes, int n_in,
                              void* d_out, int out_size)
{
    const float* aspect = (const float*)d_in[0];   // [B,1,D]
    const float* memory = (const float*)d_in[1];   // [B,S,D]
    const float* W      = (const float*)d_in[2];   // [2D,1]
    const float* bias   = (const float*)d_in[3];   // [1]
    float* out = (float*)d_out;                    // [B,D]

    att_fused<<<B_ * NSPLIT, THREADS>>>(aspect, memory, W, bias, out);
}